// round 3
// baseline (speedup 1.0000x reference)
#include <cuda_runtime.h>
#include <cstdint>

// Problem constants (fixed by the dataset)
#define NN 30000
#define EE 600000
#define HH 128
#define GG 64
#define LL 4

#define TE 64          // edges (or nodes) per CTA tile
#define AS 260         // smem row stride for A tile (words), keeps float4 alignment

// Scratch (device globals: allocation-free rule). 16B-aligned for float4 ops.
__device__ __align__(16) float g_dist[EE];       // squared distances per edge
__device__ __align__(16) float g_h[NN * HH];     // node features
__device__ __align__(16) float g_aggr[NN * HH];  // scatter-add target
__device__ __align__(16) float g_pool[GG * HH];  // per-graph pooled features

__device__ __forceinline__ float silu_f(float x) {
    return __fdividef(x, 1.0f + __expf(-x));
}

// ---------------------------------------------------------------------------
// dist_sq[e] = ||pos[row] - pos[col]||^2     (edge_index arrives as int32)
__global__ void k_dist(const float* __restrict__ pos, const int* __restrict__ ei) {
    int e = blockIdx.x * blockDim.x + threadIdx.x;
    if (e >= EE) return;
    int r = ei[e];
    int c = ei[EE + e];
    float dx = pos[r * 3 + 0] - pos[c * 3 + 0];
    float dy = pos[r * 3 + 1] - pos[c * 3 + 1];
    float dz = pos[r * 3 + 2] - pos[c * 3 + 2];
    g_dist[e] = dx * dx + dy * dy + dz * dz;
}

// h = x @ emb_w + emb_b   (x is [N,1], emb_w [1,H])
__global__ void k_embed(const float* __restrict__ x, const float* __restrict__ w,
                        const float* __restrict__ b) {
    int i = blockIdx.x * blockDim.x + threadIdx.x;
    if (i >= NN * HH) return;
    int n = i >> 7, c = i & 127;
    g_h[i] = x[n] * w[c] + b[c];
}

__global__ void k_zero_aggr() {
    int i = blockIdx.x * blockDim.x + threadIdx.x;
    if (i < NN * HH) g_aggr[i] = 0.0f;
}

__global__ void k_zero_pool() {
    int i = blockIdx.x * blockDim.x + threadIdx.x;
    if (i < GG * HH) g_pool[i] = 0.0f;
}

// ---------------------------------------------------------------------------
// Fused edge message MLP + scatter-add.
// Per CTA: 64 edges. A = [x_i | x_j | d2]  (64 x 257) in smem.
// C1 = silu(A @ W1 + b1)  (64 x 128), kept in smem (overwrites A[:, :128]).
// C2 = C1 @ W2 + b2       (64 x 128), atomically added into aggr[col].
__global__ __launch_bounds__(256) void k_edge(
    const int* __restrict__ ei,
    const float* __restrict__ w1, const float* __restrict__ b1,
    const float* __restrict__ w2, const float* __restrict__ b2)
{
    extern __shared__ float sm[];
    float* sA = sm;                      // TE * AS floats
    float* sW = sm + TE * AS;            // 8 * HH floats
    int* sCol = (int*)(sW + 8 * HH);     // TE ints

    const int tid = threadIdx.x;
    const int warp = tid >> 5, lane = tid & 31;
    const int tx = tid & 15, ty = tid >> 4;
    const int ebase = blockIdx.x * TE;

    // Gather: each warp fills 8 edge rows (coalesced float4 row loads)
    #pragma unroll
    for (int i = 0; i < 8; i++) {
        int el = warp * 8 + i;
        int e = ebase + el;
        int src = ei[e];        // row  = source j
        int dst = ei[EE + e];   // col  = target i
        float4 vi = *(const float4*)(g_h + (size_t)dst * HH + lane * 4);
        float4 vj = *(const float4*)(g_h + (size_t)src * HH + lane * 4);
        *(float4*)(sA + el * AS + lane * 4) = vi;
        *(float4*)(sA + el * AS + 128 + lane * 4) = vj;
        if (lane == 0) { sA[el * AS + 256] = g_dist[e]; sCol[el] = dst; }
    }
    __syncthreads();

    float acc[4][8];
    #pragma unroll
    for (int i = 0; i < 4; i++)
        #pragma unroll
        for (int j = 0; j < 8; j++) acc[i][j] = 0.0f;

    // GEMM1: K = 257 (32 chunks of 8 + remainder row 256)
    for (int k0 = 0; k0 < 256; k0 += 8) {
        float4 wv = *(const float4*)(w1 + (size_t)k0 * HH + tid * 4);
        __syncthreads();
        *(float4*)(sW + tid * 4) = wv;
        __syncthreads();
        #pragma unroll
        for (int kk = 0; kk < 8; kk++) {
            float a0 = sA[(ty     ) * AS + k0 + kk];
            float a1 = sA[(ty + 16) * AS + k0 + kk];
            float a2 = sA[(ty + 32) * AS + k0 + kk];
            float a3 = sA[(ty + 48) * AS + k0 + kk];
            #pragma unroll
            for (int j = 0; j < 8; j++) {
                float w = sW[kk * HH + tx + 16 * j];
                acc[0][j] += a0 * w;
                acc[1][j] += a1 * w;
                acc[2][j] += a2 * w;
                acc[3][j] += a3 * w;
            }
        }
    }
    {   // remainder k = 256 (dist column)
        const float* wr = w1 + (size_t)256 * HH;
        float a0 = sA[(ty     ) * AS + 256];
        float a1 = sA[(ty + 16) * AS + 256];
        float a2 = sA[(ty + 32) * AS + 256];
        float a3 = sA[(ty + 48) * AS + 256];
        #pragma unroll
        for (int j = 0; j < 8; j++) {
            float w = wr[tx + 16 * j];
            acc[0][j] += a0 * w; acc[1][j] += a1 * w;
            acc[2][j] += a2 * w; acc[3][j] += a3 * w;
        }
    }
    __syncthreads();
    // bias + silu -> written back into sA[:, 0:128]
    #pragma unroll
    for (int j = 0; j < 8; j++) {
        float bb = b1[tx + 16 * j];
        #pragma unroll
        for (int i = 0; i < 4; i++) {
            sA[(ty + 16 * i) * AS + tx + 16 * j] = silu_f(acc[i][j] + bb);
            acc[i][j] = 0.0f;
        }
    }
    __syncthreads();

    // GEMM2: K = 128
    for (int k0 = 0; k0 < 128; k0 += 8) {
        float4 wv = *(const float4*)(w2 + (size_t)k0 * HH + tid * 4);
        __syncthreads();
        *(float4*)(sW + tid * 4) = wv;
        __syncthreads();
        #pragma unroll
        for (int kk = 0; kk < 8; kk++) {
            float a0 = sA[(ty     ) * AS + k0 + kk];
            float a1 = sA[(ty + 16) * AS + k0 + kk];
            float a2 = sA[(ty + 32) * AS + k0 + kk];
            float a3 = sA[(ty + 48) * AS + k0 + kk];
            #pragma unroll
            for (int j = 0; j < 8; j++) {
                float w = sW[kk * HH + tx + 16 * j];
                acc[0][j] += a0 * w;
                acc[1][j] += a1 * w;
                acc[2][j] += a2 * w;
                acc[3][j] += a3 * w;
            }
        }
    }

    // bias + scatter-add into aggr[col]
    #pragma unroll
    for (int i = 0; i < 4; i++) {
        float* base = g_aggr + (size_t)sCol[ty + 16 * i] * HH;
        #pragma unroll
        for (int j = 0; j < 8; j++) {
            atomicAdd(base + tx + 16 * j, acc[i][j] + b2[tx + 16 * j]);
        }
    }
}

// ---------------------------------------------------------------------------
// Fused node-update MLP. A = [h | aggr] (64 x 256). h_new = silu(A@W1+b1)@W2+b2.
__global__ __launch_bounds__(256) void k_node(
    const float* __restrict__ w1, const float* __restrict__ b1,
    const float* __restrict__ w2, const float* __restrict__ b2)
{
    extern __shared__ float sm[];
    float* sA = sm;
    float* sW = sm + TE * AS;

    const int tid = threadIdx.x;
    const int warp = tid >> 5, lane = tid & 31;
    const int tx = tid & 15, ty = tid >> 4;
    const int nbase = blockIdx.x * TE;

    #pragma unroll
    for (int i = 0; i < 8; i++) {
        int el = warp * 8 + i;
        int n = nbase + el;
        if (n < NN) {
            float4 vh = *(const float4*)(g_h + (size_t)n * HH + lane * 4);
            float4 va = *(const float4*)(g_aggr + (size_t)n * HH + lane * 4);
            *(float4*)(sA + el * AS + lane * 4) = vh;
            *(float4*)(sA + el * AS + 128 + lane * 4) = va;
        } else {
            float4 z = make_float4(0.f, 0.f, 0.f, 0.f);
            *(float4*)(sA + el * AS + lane * 4) = z;
            *(float4*)(sA + el * AS + 128 + lane * 4) = z;
        }
    }
    __syncthreads();

    float acc[4][8];
    #pragma unroll
    for (int i = 0; i < 4; i++)
        #pragma unroll
        for (int j = 0; j < 8; j++) acc[i][j] = 0.0f;

    // GEMM1: K = 256
    for (int k0 = 0; k0 < 256; k0 += 8) {
        float4 wv = *(const float4*)(w1 + (size_t)k0 * HH + tid * 4);
        __syncthreads();
        *(float4*)(sW + tid * 4) = wv;
        __syncthreads();
        #pragma unroll
        for (int kk = 0; kk < 8; kk++) {
            float a0 = sA[(ty     ) * AS + k0 + kk];
            float a1 = sA[(ty + 16) * AS + k0 + kk];
            float a2 = sA[(ty + 32) * AS + k0 + kk];
            float a3 = sA[(ty + 48) * AS + k0 + kk];
            #pragma unroll
            for (int j = 0; j < 8; j++) {
                float w = sW[kk * HH + tx + 16 * j];
                acc[0][j] += a0 * w;
                acc[1][j] += a1 * w;
                acc[2][j] += a2 * w;
                acc[3][j] += a3 * w;
            }
        }
    }
    __syncthreads();
    #pragma unroll
    for (int j = 0; j < 8; j++) {
        float bb = b1[tx + 16 * j];
        #pragma unroll
        for (int i = 0; i < 4; i++) {
            sA[(ty + 16 * i) * AS + tx + 16 * j] = silu_f(acc[i][j] + bb);
            acc[i][j] = 0.0f;
        }
    }
    __syncthreads();

    // GEMM2: K = 128
    for (int k0 = 0; k0 < 128; k0 += 8) {
        float4 wv = *(const float4*)(w2 + (size_t)k0 * HH + tid * 4);
        __syncthreads();
        *(float4*)(sW + tid * 4) = wv;
        __syncthreads();
        #pragma unroll
        for (int kk = 0; kk < 8; kk++) {
            float a0 = sA[(ty     ) * AS + k0 + kk];
            float a1 = sA[(ty + 16) * AS + k0 + kk];
            float a2 = sA[(ty + 32) * AS + k0 + kk];
            float a3 = sA[(ty + 48) * AS + k0 + kk];
            #pragma unroll
            for (int j = 0; j < 8; j++) {
                float w = sW[kk * HH + tx + 16 * j];
                acc[0][j] += a0 * w;
                acc[1][j] += a1 * w;
                acc[2][j] += a2 * w;
                acc[3][j] += a3 * w;
            }
        }
    }

    #pragma unroll
    for (int i = 0; i < 4; i++) {
        int n = nbase + ty + 16 * i;
        if (n < NN) {
            #pragma unroll
            for (int j = 0; j < 8; j++) {
                g_h[(size_t)n * HH + tx + 16 * j] = acc[i][j] + b2[tx + 16 * j];
            }
        }
    }
}

// ---------------------------------------------------------------------------
// global_add_pool: g_pool[batch[n]] += h[n]   (batch arrives as int32)
__global__ void k_pool(const int* __restrict__ batch) {
    int i = blockIdx.x * blockDim.x + threadIdx.x;
    if (i >= NN * 32) return;
    int n = i >> 5, c4 = (i & 31) * 4;
    int b = batch[n];
    const float* hr = g_h + (size_t)n * HH + c4;
    float* pr = g_pool + (size_t)b * HH + c4;
    atomicAdd(pr + 0, hr[0]);
    atomicAdd(pr + 1, hr[1]);
    atomicAdd(pr + 2, hr[2]);
    atomicAdd(pr + 3, hr[3]);
}

// Output head: out = silu(g @ W1 + b1) @ W2 + b2   (tiny: 64x128 -> 64x32 -> 64)
__global__ void k_out(const float* __restrict__ w1, const float* __restrict__ b1,
                      const float* __restrict__ w2, const float* __restrict__ b2,
                      float* __restrict__ out) {
    __shared__ float sg[GG * HH];   // 32 KB
    __shared__ float sh[GG * 32];   // 8 KB
    int tid = threadIdx.x;
    for (int i = tid; i < GG * HH; i += 256) sg[i] = g_pool[i];
    __syncthreads();
    for (int p = tid; p < GG * 32; p += 256) {
        int g = p >> 5, j = p & 31;
        float s = b1[j];
        #pragma unroll 4
        for (int k = 0; k < HH; k++) s += sg[g * HH + k] * w1[k * 32 + j];
        sh[p] = silu_f(s);
    }
    __syncthreads();
    if (tid < GG) {
        float s = b2[0];
        #pragma unroll
        for (int j = 0; j < 32; j++) s += sh[tid * 32 + j] * w2[j];
        out[tid] = s;
    }
}

// ---------------------------------------------------------------------------
extern "C" void kernel_launch(void* const* d_in, const int* in_sizes, int n_in,
                              void* d_out, int out_size) {
    const float* x       = (const float*)d_in[0];
    const float* pos     = (const float*)d_in[1];
    const int*   ei      = (const int*)d_in[2];
    const int*   batch   = (const int*)d_in[3];
    const float* emb_w   = (const float*)d_in[4];
    const float* emb_b   = (const float*)d_in[5];
    const float* msg_w1  = (const float*)d_in[6];
    const float* msg_b1  = (const float*)d_in[7];
    const float* msg_w2  = (const float*)d_in[8];
    const float* msg_b2  = (const float*)d_in[9];
    const float* node_w1 = (const float*)d_in[10];
    const float* node_b1 = (const float*)d_in[11];
    const float* node_w2 = (const float*)d_in[12];
    const float* node_b2 = (const float*)d_in[13];
    const float* out_w1  = (const float*)d_in[14];
    const float* out_b1  = (const float*)d_in[15];
    const float* out_w2  = (const float*)d_in[16];
    const float* out_b2  = (const float*)d_in[17];
    float* out = (float*)d_out;

    const int SMEM_EDGE = (TE * AS + 8 * HH) * 4 + TE * 4;  // 70912 B
    const int SMEM_NODE = (TE * AS + 8 * HH) * 4;           // 70656 B
    cudaFuncSetAttribute(k_edge, cudaFuncAttributeMaxDynamicSharedMemorySize, SMEM_EDGE);
    cudaFuncSetAttribute(k_node, cudaFuncAttributeMaxDynamicSharedMemorySize, SMEM_NODE);

    k_dist<<<(EE + 255) / 256, 256>>>(pos, ei);
    k_embed<<<(NN * HH + 255) / 256, 256>>>(x, emb_w, emb_b);

    for (int l = 0; l < LL; l++) {
        k_zero_aggr<<<(NN * HH + 255) / 256, 256>>>();
        k_edge<<<EE / TE, 256, SMEM_EDGE>>>(
            ei,
            msg_w1 + (size_t)l * (2 * HH + 1) * HH, msg_b1 + (size_t)l * HH,
            msg_w2 + (size_t)l * HH * HH,           msg_b2 + (size_t)l * HH);
        k_node<<<(NN + TE - 1) / TE, 256, SMEM_NODE>>>(
            node_w1 + (size_t)l * 2 * HH * HH, node_b1 + (size_t)l * HH,
            node_w2 + (size_t)l * HH * HH,     node_b2 + (size_t)l * HH);
    }

    k_zero_pool<<<(GG * HH + 255) / 256, 256>>>();
    k_pool<<<(NN * 32 + 255) / 256, 256>>>(batch);
    k_out<<<1, 256>>>(out_w1, out_b1, out_w2, out_b2, out);
}